// round 12
// baseline (speedup 1.0000x reference)
#include <cuda_runtime.h>
#include <cuda_fp16.h>
#include <cuda_fp8.h>
#include <cstdint>

// ---------------------------------------------------------------------------
// out[M,N] = (fp8(x*xs) @ fp8(w^T*ws)^T) * (1/xs)*(1/ws), fp32 out
// M=16384, N=4096, K=4096
// R12: R5 protocol (wait+sync every iter — REQUIRED for cp.async cross-warp
// visibility), R5 warp shape (64x32) and 16 warps/SM, but CTA 128x256 with
// 512 threads / 16 warps, 3-stage ring (144KB), 1 CTA/SM. Doubles tensor
// work per barrier -> halves the per-iteration sync/ramp overhead fraction.
// 4 launches so ncu (-s 5) lands on the GEMM.
// ---------------------------------------------------------------------------
#define MDIM 16384
#define NDIM 4096
#define KDIM 4096

#define BM 128
#define BN 256
#define BK 64                // fp16 elements per stage row (128 bytes)
#define STAGES 3
#define KITERS (KDIM / BK)   // 64

#define SWZ(o) ((o) ^ (((o) >> 3) & 0x70))

// ---------------------------------------------------------------------------
// Device scratch (allocation-free)
// ---------------------------------------------------------------------------
__device__ __align__(1024) __half g_xh[(size_t)MDIM * KDIM]; // 128 MB
__device__ __align__(1024) __half g_wh[(size_t)NDIM * KDIM]; // 32 MB
__device__ unsigned int g_amax_bits[2] = {0u, 0u};           // scale_kernel re-zeros
__device__ float g_scales[3];                                // xs, ws, (1/xs)*(1/ws)

// ---------------------------------------------------------------------------
// PTX helpers
// ---------------------------------------------------------------------------
__device__ __forceinline__ uint32_t smem_u32(const void* p) {
    uint32_t a;
    asm("{ .reg .u64 t; cvta.to.shared.u64 t, %1; cvt.u32.u64 %0, t; }" : "=r"(a) : "l"(p));
    return a;
}

#define CP_ASYNC16(dst, gsrc) \
    asm volatile("cp.async.cg.shared.global [%0], [%1], 16;" :: "r"(dst), "l"(gsrc) : "memory")
#define CP_COMMIT() asm volatile("cp.async.commit_group;" ::: "memory")
#define CP_WAIT(n)  asm volatile("cp.async.wait_group %0;" :: "n"(n) : "memory")

#define LDSM_X4(r0, r1, r2, r3, addr) \
    asm volatile("ldmatrix.sync.aligned.m8n8.x4.shared.b16 {%0,%1,%2,%3}, [%4];" \
        : "=r"(r0), "=r"(r1), "=r"(r2), "=r"(r3) : "r"(addr))

#define MMA16816(c, a, b) \
    asm volatile("mma.sync.aligned.m16n8k16.row.col.f32.f16.f16.f32 " \
        "{%0,%1,%2,%3}, {%4,%5,%6,%7}, {%8,%9}, {%0,%1,%2,%3};" \
        : "+f"((c)[0]), "+f"((c)[1]), "+f"((c)[2]), "+f"((c)[3]) \
        : "r"((a)[0]), "r"((a)[1]), "r"((a)[2]), "r"((a)[3]), "r"((b)[0]), "r"((b)[1]))

// ---------------------------------------------------------------------------
// Launch 0: fused amax (x: blocks 0..2047, w: blocks 2048..2559)
// ---------------------------------------------------------------------------
__global__ void amax_all_kernel(const float* __restrict__ x, const float* __restrict__ w) {
    int slot;
    const float4* v;
    long long n4, b0, nb;
    if (blockIdx.x < 2048) {
        slot = 0; v = (const float4*)x; n4 = (long long)MDIM * KDIM / 4; b0 = blockIdx.x; nb = 2048;
    } else {
        slot = 1; v = (const float4*)w; n4 = (long long)KDIM * NDIM / 4; b0 = blockIdx.x - 2048; nb = 512;
    }
    float m = 0.0f;
    long long stride = nb * blockDim.x;
    for (long long i = b0 * blockDim.x + threadIdx.x; i < n4; i += stride) {
        float4 a = v[i];
        m = fmaxf(m, fmaxf(fmaxf(fabsf(a.x), fabsf(a.y)), fmaxf(fabsf(a.z), fabsf(a.w))));
    }
    #pragma unroll
    for (int o = 16; o; o >>= 1) m = fmaxf(m, __shfl_xor_sync(0xFFFFFFFFu, m, o));
    __shared__ float sm[32];
    if ((threadIdx.x & 31) == 0) sm[threadIdx.x >> 5] = m;
    __syncthreads();
    if (threadIdx.x < 32) {
        m = (threadIdx.x < (blockDim.x >> 5)) ? sm[threadIdx.x] : 0.0f;
        #pragma unroll
        for (int o = 16; o; o >>= 1) m = fmaxf(m, __shfl_xor_sync(0xFFFFFFFFu, m, o));
        if (threadIdx.x == 0) atomicMax(&g_amax_bits[slot], __float_as_uint(m));
    }
}

// ---------------------------------------------------------------------------
// Launch 1: scales + reset accumulators (idempotent across graph replays)
// ---------------------------------------------------------------------------
__global__ void scale_kernel() {
    float ax = __uint_as_float(g_amax_bits[0]);
    float aw = __uint_as_float(g_amax_bits[1]);
    float xs = 448.0f / fmaxf(ax, 1e-12f);
    float ws = 448.0f / fmaxf(aw, 1e-12f);
    g_scales[0] = xs;
    g_scales[1] = ws;
    g_scales[2] = (1.0f / xs) * (1.0f / ws);
    g_amax_bits[0] = 0u;
    g_amax_bits[1] = 0u;
}

__device__ __forceinline__ unsigned short q8h(float v, float s) {
    __nv_fp8_storage_t r = __nv_cvt_float_to_fp8(v * s, __NV_SATFINITE, __NV_E4M3);
    __half_raw hr = __nv_cvt_fp8_to_halfraw(r, __NV_E4M3);
    return hr.x;
}

// ---------------------------------------------------------------------------
// Launch 2: fused quantize. Blocks [0,32768): x (8 elems/thread).
// Blocks [32768, 32768+1024): w transpose 128x128 tiles.
// ---------------------------------------------------------------------------
__global__ void quant_all_kernel(const float* __restrict__ x, const float* __restrict__ w) {
    if (blockIdx.x < 32768) {
        size_t i = ((size_t)blockIdx.x * blockDim.x + threadIdx.x) * 8;
        float s = g_scales[0];
        float4 v0 = *(const float4*)(x + i);
        float4 v1 = *(const float4*)(x + i + 4);
        uint4 packed;
        packed.x = (uint32_t)q8h(v0.x, s) | ((uint32_t)q8h(v0.y, s) << 16);
        packed.y = (uint32_t)q8h(v0.z, s) | ((uint32_t)q8h(v0.w, s) << 16);
        packed.z = (uint32_t)q8h(v1.x, s) | ((uint32_t)q8h(v1.y, s) << 16);
        packed.w = (uint32_t)q8h(v1.z, s) | ((uint32_t)q8h(v1.w, s) << 16);
        *(uint4*)(g_xh + i) = packed;
    } else {
        __shared__ unsigned short sbuf[128 * 129];
        int t = blockIdx.x - 32768;
        int k0 = (t & 31) * 128;
        int n0 = (t >> 5) * 128;
        float ws = g_scales[1];
        #pragma unroll 4
        for (int it = 0; it < 16; ++it) {
            int p = it * 1024 + threadIdx.x * 4;
            int kl = p >> 7, nl = p & 127;
            float4 v = *(const float4*)&w[(size_t)(k0 + kl) * NDIM + n0 + nl];
            sbuf[kl * 129 + nl + 0] = q8h(v.x, ws);
            sbuf[kl * 129 + nl + 1] = q8h(v.y, ws);
            sbuf[kl * 129 + nl + 2] = q8h(v.z, ws);
            sbuf[kl * 129 + nl + 3] = q8h(v.w, ws);
        }
        __syncthreads();
        #pragma unroll 2
        for (int it = 0; it < 8; ++it) {
            int tt = it * 256 + threadIdx.x;
            int nl = tt >> 4, kg = tt & 15;
            unsigned short h[8];
            #pragma unroll
            for (int i = 0; i < 8; ++i) h[i] = sbuf[(kg * 8 + i) * 129 + nl];
            uint4 packed;
            packed.x = (uint32_t)h[0] | ((uint32_t)h[1] << 16);
            packed.y = (uint32_t)h[2] | ((uint32_t)h[3] << 16);
            packed.z = (uint32_t)h[4] | ((uint32_t)h[5] << 16);
            packed.w = (uint32_t)h[6] | ((uint32_t)h[7] << 16);
            *(uint4*)(g_wh + (size_t)(n0 + nl) * KDIM + k0 + kg * 8) = packed;
        }
    }
}

// ---------------------------------------------------------------------------
// Launch 3: GEMM. A = g_xh [M,K], B = g_wh [N,K] (TN).
// CTA 128x256, 512 threads = 16 warps of 64x32 (2 M x 8 N), 3-stage ring,
// R5 protocol: CP_WAIT + __syncthreads every iteration, then load next.
// ---------------------------------------------------------------------------
#define A_STAGE_BYTES (BM * BK * 2)          // 16384
#define B_STAGE_BYTES (BN * BK * 2)          // 32768
#define SMEM_TOTAL (STAGES * (A_STAGE_BYTES + B_STAGE_BYTES))  // 147456

__global__ void __launch_bounds__(512, 1) gemm_kernel(float* __restrict__ out) {
    extern __shared__ char smem[];
    const uint32_t sb = smem_u32(smem);
    const int tid = threadIdx.x;
    const int lane = tid & 31;
    const int wid = tid >> 5;        // 0..15
    const int warp_m = wid & 1;      // 2 warps along M (64 rows)
    const int warp_n = wid >> 1;     // 8 warps along N (32 cols each)
    const int m0 = blockIdx.y * BM;
    const int n0 = blockIdx.x * BN;

    const uint64_t Ag = __cvta_generic_to_global(g_xh + (size_t)m0 * KDIM);
    const uint64_t Bg = __cvta_generic_to_global(g_wh + (size_t)n0 * KDIM);

    // one stage: A 128 rows x 8 chunks of 16B (1024) + B 256 rows x 8 (2048)
    auto load_stage = [&](int stage, int kblk) {
        uint32_t abase = sb + stage * A_STAGE_BYTES;
        uint32_t bbase = sb + STAGES * A_STAGE_BYTES + stage * B_STAGE_BYTES;
        uint64_t koff = (uint64_t)kblk * (BK * 2);
        #pragma unroll
        for (int i = 0; i < 2; ++i) {
            int c = tid + i * 512;
            int row = c >> 3, col = c & 7;
            CP_ASYNC16(abase + SWZ(row * 128 + col * 16),
                       Ag + (uint64_t)row * (KDIM * 2) + koff + col * 16);
        }
        #pragma unroll
        for (int i = 0; i < 4; ++i) {
            int c = tid + i * 512;
            int row = c >> 3, col = c & 7;
            CP_ASYNC16(bbase + SWZ(row * 128 + col * 16),
                       Bg + (uint64_t)row * (KDIM * 2) + koff + col * 16);
        }
        CP_COMMIT();
    };

    load_stage(0, 0);
    load_stage(1, 1);

    float acc[4][4][4];
    #pragma unroll
    for (int mi = 0; mi < 4; ++mi)
        #pragma unroll
        for (int nj = 0; nj < 4; ++nj)
            #pragma unroll
            for (int r = 0; r < 4; ++r) acc[mi][nj][r] = 0.0f;

    const uint32_t a_row = warp_m * 64 + (lane & 15);
    const uint32_t a_kb  = (uint32_t)((lane >> 4) << 4);
    const uint32_t b_n   = warp_n * 32 + (lane & 7) + ((lane >> 4) << 3);
    const uint32_t b_kb  = (uint32_t)(((lane >> 3) & 1) << 4);

    int stage = 0;
    #pragma unroll 1
    for (int it = 0; it < KITERS; ++it) {
        CP_WAIT(1);
        __syncthreads();
        if (it + 2 < KITERS) {
            int ps = stage + 2;
            if (ps >= STAGES) ps -= STAGES;
            load_stage(ps, it + 2);
        }

        uint32_t abase = sb + stage * A_STAGE_BYTES;
        uint32_t bbase = sb + STAGES * A_STAGE_BYTES + stage * B_STAGE_BYTES;

        #pragma unroll
        for (int ks = 0; ks < 4; ++ks) {
            uint32_t a[4][4], b[4][2];
            #pragma unroll
            for (int mi = 0; mi < 4; ++mi) {
                uint32_t off = (a_row + mi * 16) * 128 + ks * 32 + a_kb;
                LDSM_X4(a[mi][0], a[mi][1], a[mi][2], a[mi][3], abase + SWZ(off));
            }
            #pragma unroll
            for (int bh = 0; bh < 2; ++bh) {
                uint32_t off = (b_n + bh * 16) * 128 + ks * 32 + b_kb;
                LDSM_X4(b[2 * bh][0], b[2 * bh][1], b[2 * bh + 1][0], b[2 * bh + 1][1],
                        bbase + SWZ(off));
            }
            #pragma unroll
            for (int mi = 0; mi < 4; ++mi)
                #pragma unroll
                for (int nj = 0; nj < 4; ++nj)
                    MMA16816(acc[mi][nj], a[mi], b[nj]);
        }
        stage = (stage + 1 == STAGES) ? 0 : stage + 1;
    }

    // epilogue: scale + store fp32
    const float cs = g_scales[2];
    const int row_base = m0 + warp_m * 64 + (lane >> 2);
    const int col_base = n0 + warp_n * 32 + (lane & 3) * 2;
    #pragma unroll
    for (int mi = 0; mi < 4; ++mi) {
        #pragma unroll
        for (int nj = 0; nj < 4; ++nj) {
            int r = row_base + mi * 16;
            int c = col_base + nj * 8;
            float2 v0 = make_float2(acc[mi][nj][0] * cs, acc[mi][nj][1] * cs);
            float2 v1 = make_float2(acc[mi][nj][2] * cs, acc[mi][nj][3] * cs);
            *(float2*)(out + (size_t)r * NDIM + c) = v0;
            *(float2*)(out + (size_t)(r + 8) * NDIM + c) = v1;
        }
    }
}

// ---------------------------------------------------------------------------
// Launch: exactly 4 kernels
// ---------------------------------------------------------------------------
extern "C" void kernel_launch(void* const* d_in, const int* in_sizes, int n_in,
                              void* d_out, int out_size) {
    const float* x = (const float*)d_in[0];
    const float* w = (const float*)d_in[1];
    float* out = (float*)d_out;

    cudaFuncSetAttribute(gemm_kernel, cudaFuncAttributeMaxDynamicSharedMemorySize, SMEM_TOTAL);

    amax_all_kernel<<<2560, 256>>>(x, w);
    scale_kernel<<<1, 1>>>();
    quant_all_kernel<<<32768 + 1024, 256>>>(x, w);
    gemm_kernel<<<dim3(NDIM / BN, MDIM / BM), 512, SMEM_TOTAL>>>(out);
}

// round 13
// speedup vs baseline: 1.1126x; 1.1126x over previous
#include <cuda_runtime.h>
#include <cuda_fp16.h>
#include <cuda_fp8.h>
#include <cstdint>

// ---------------------------------------------------------------------------
// out[M,N] = (fp8(x*xs) @ fp8(w^T*ws)^T) * (1/xs)*(1/ws), fp32 out
// M=16384, N=4096, K=4096
// R13: R5 GEMM (CTA 128x128, 8 warps 64x32, fp16 HMMA, 3 stages, 2 CTA/SM)
// with the per-iteration __syncthreads replaced by per-stage mbarrier
// producer/consumer pipelines (sm_80/90-portable PTX):
//   producer: wait empty[s] -> cp.async -> cp.async.mbarrier.arrive.noinc full[s]
//   consumer: try_wait full[s] (acquire) -> LDSM/MMA -> arrive empty[s]
// Warps may skew up to 2 stages instead of hard lockstep -> fills the
// barrier bubbles behind R5's 18% tensor idle.
// 4 launches so ncu (-s 5) lands on the GEMM.
// ---------------------------------------------------------------------------
#define MDIM 16384
#define NDIM 4096
#define KDIM 4096

#define BM 128
#define BN 128
#define BK 64                // fp16 elements per stage row (128 bytes)
#define STAGES 3
#define KITERS (KDIM / BK)   // 64

#define SWZ(o) ((o) ^ (((o) >> 3) & 0x70))

// ---------------------------------------------------------------------------
// Device scratch (allocation-free)
// ---------------------------------------------------------------------------
__device__ __align__(1024) __half g_xh[(size_t)MDIM * KDIM]; // 128 MB
__device__ __align__(1024) __half g_wh[(size_t)NDIM * KDIM]; // 32 MB
__device__ unsigned int g_amax_bits[2] = {0u, 0u};           // scale_kernel re-zeros
__device__ float g_scales[3];                                // xs, ws, (1/xs)*(1/ws)

// ---------------------------------------------------------------------------
// PTX helpers
// ---------------------------------------------------------------------------
__device__ __forceinline__ uint32_t smem_u32(const void* p) {
    uint32_t a;
    asm("{ .reg .u64 t; cvta.to.shared.u64 t, %1; cvt.u32.u64 %0, t; }" : "=r"(a) : "l"(p));
    return a;
}

#define CP_ASYNC16(dst, gsrc) \
    asm volatile("cp.async.cg.shared.global [%0], [%1], 16;" :: "r"(dst), "l"(gsrc) : "memory")

// one arrive on mbar when ALL prior cp.asyncs of this thread complete
#define CP_ASYNC_MBAR_ARRIVE(mbar) \
    asm volatile("cp.async.mbarrier.arrive.noinc.shared::cta.b64 [%0];" \
        :: "r"((uint32_t)(mbar)) : "memory")

#define MBARRIER_INIT(mbar, count) \
    asm volatile("mbarrier.init.shared.b64 [%0], %1;" \
        :: "r"((uint32_t)(mbar)), "r"((uint32_t)(count)) : "memory")
#define MBARRIER_ARRIVE(mbar) \
    asm volatile("mbarrier.arrive.shared.b64 _, [%0];" \
        :: "r"((uint32_t)(mbar)) : "memory")

#define MBAR_WAIT(mbar, parity) do { \
    uint32_t _m = (uint32_t)(mbar); uint32_t _p = (uint32_t)(parity); uint32_t _d; \
    asm volatile("{\n\t.reg .pred p;\n\t" \
        "mbarrier.try_wait.parity.acquire.cta.shared::cta.b64 p, [%1], %2;\n\t" \
        "selp.b32 %0, 1, 0, p;\n\t}" : "=r"(_d) : "r"(_m), "r"(_p) : "memory"); \
    if (!_d) { \
        asm volatile("{\n\t.reg .pred P1;\n\t" \
            "WL_%=:\n\t" \
            "mbarrier.try_wait.parity.acquire.cta.shared::cta.b64 P1, [%0], %1, 0x989680;\n\t" \
            "@P1 bra.uni WD_%=;\n\t" \
            "bra.uni WL_%=;\n\t" \
            "WD_%=:\n\t}" :: "r"(_m), "r"(_p) : "memory"); \
    } \
} while (0)

#define LDSM_X4(r0, r1, r2, r3, addr) \
    asm volatile("ldmatrix.sync.aligned.m8n8.x4.shared.b16 {%0,%1,%2,%3}, [%4];" \
        : "=r"(r0), "=r"(r1), "=r"(r2), "=r"(r3) : "r"(addr))

#define MMA16816(c, a, b) \
    asm volatile("mma.sync.aligned.m16n8k16.row.col.f32.f16.f16.f32 " \
        "{%0,%1,%2,%3}, {%4,%5,%6,%7}, {%8,%9}, {%0,%1,%2,%3};" \
        : "+f"((c)[0]), "+f"((c)[1]), "+f"((c)[2]), "+f"((c)[3]) \
        : "r"((a)[0]), "r"((a)[1]), "r"((a)[2]), "r"((a)[3]), "r"((b)[0]), "r"((b)[1]))

// ---------------------------------------------------------------------------
// Launch 0: fused amax (x: blocks 0..2047, w: blocks 2048..2559)
// ---------------------------------------------------------------------------
__global__ void amax_all_kernel(const float* __restrict__ x, const float* __restrict__ w) {
    int slot;
    const float4* v;
    long long n4, b0, nb;
    if (blockIdx.x < 2048) {
        slot = 0; v = (const float4*)x; n4 = (long long)MDIM * KDIM / 4; b0 = blockIdx.x; nb = 2048;
    } else {
        slot = 1; v = (const float4*)w; n4 = (long long)KDIM * NDIM / 4; b0 = blockIdx.x - 2048; nb = 512;
    }
    float m = 0.0f;
    long long stride = nb * blockDim.x;
    for (long long i = b0 * blockDim.x + threadIdx.x; i < n4; i += stride) {
        float4 a = v[i];
        m = fmaxf(m, fmaxf(fmaxf(fabsf(a.x), fabsf(a.y)), fmaxf(fabsf(a.z), fabsf(a.w))));
    }
    #pragma unroll
    for (int o = 16; o; o >>= 1) m = fmaxf(m, __shfl_xor_sync(0xFFFFFFFFu, m, o));
    __shared__ float sm[32];
    if ((threadIdx.x & 31) == 0) sm[threadIdx.x >> 5] = m;
    __syncthreads();
    if (threadIdx.x < 32) {
        m = (threadIdx.x < (blockDim.x >> 5)) ? sm[threadIdx.x] : 0.0f;
        #pragma unroll
        for (int o = 16; o; o >>= 1) m = fmaxf(m, __shfl_xor_sync(0xFFFFFFFFu, m, o));
        if (threadIdx.x == 0) atomicMax(&g_amax_bits[slot], __float_as_uint(m));
    }
}

// ---------------------------------------------------------------------------
// Launch 1: scales + reset accumulators (idempotent across graph replays)
// ---------------------------------------------------------------------------
__global__ void scale_kernel() {
    float ax = __uint_as_float(g_amax_bits[0]);
    float aw = __uint_as_float(g_amax_bits[1]);
    float xs = 448.0f / fmaxf(ax, 1e-12f);
    float ws = 448.0f / fmaxf(aw, 1e-12f);
    g_scales[0] = xs;
    g_scales[1] = ws;
    g_scales[2] = (1.0f / xs) * (1.0f / ws);
    g_amax_bits[0] = 0u;
    g_amax_bits[1] = 0u;
}

__device__ __forceinline__ unsigned short q8h(float v, float s) {
    __nv_fp8_storage_t r = __nv_cvt_float_to_fp8(v * s, __NV_SATFINITE, __NV_E4M3);
    __half_raw hr = __nv_cvt_fp8_to_halfraw(r, __NV_E4M3);
    return hr.x;
}

// ---------------------------------------------------------------------------
// Launch 2: fused quantize. Blocks [0,32768): x (8 elems/thread).
// Blocks [32768, 32768+1024): w transpose 128x128 tiles.
// ---------------------------------------------------------------------------
__global__ void quant_all_kernel(const float* __restrict__ x, const float* __restrict__ w) {
    if (blockIdx.x < 32768) {
        size_t i = ((size_t)blockIdx.x * blockDim.x + threadIdx.x) * 8;
        float s = g_scales[0];
        float4 v0 = *(const float4*)(x + i);
        float4 v1 = *(const float4*)(x + i + 4);
        uint4 packed;
        packed.x = (uint32_t)q8h(v0.x, s) | ((uint32_t)q8h(v0.y, s) << 16);
        packed.y = (uint32_t)q8h(v0.z, s) | ((uint32_t)q8h(v0.w, s) << 16);
        packed.z = (uint32_t)q8h(v1.x, s) | ((uint32_t)q8h(v1.y, s) << 16);
        packed.w = (uint32_t)q8h(v1.z, s) | ((uint32_t)q8h(v1.w, s) << 16);
        *(uint4*)(g_xh + i) = packed;
    } else {
        __shared__ unsigned short sbuf[128 * 129];
        int t = blockIdx.x - 32768;
        int k0 = (t & 31) * 128;
        int n0 = (t >> 5) * 128;
        float ws = g_scales[1];
        #pragma unroll 4
        for (int it = 0; it < 16; ++it) {
            int p = it * 1024 + threadIdx.x * 4;
            int kl = p >> 7, nl = p & 127;
            float4 v = *(const float4*)&w[(size_t)(k0 + kl) * NDIM + n0 + nl];
            sbuf[kl * 129 + nl + 0] = q8h(v.x, ws);
            sbuf[kl * 129 + nl + 1] = q8h(v.y, ws);
            sbuf[kl * 129 + nl + 2] = q8h(v.z, ws);
            sbuf[kl * 129 + nl + 3] = q8h(v.w, ws);
        }
        __syncthreads();
        #pragma unroll 2
        for (int it = 0; it < 8; ++it) {
            int tt = it * 256 + threadIdx.x;
            int nl = tt >> 4, kg = tt & 15;
            unsigned short h[8];
            #pragma unroll
            for (int i = 0; i < 8; ++i) h[i] = sbuf[(kg * 8 + i) * 129 + nl];
            uint4 packed;
            packed.x = (uint32_t)h[0] | ((uint32_t)h[1] << 16);
            packed.y = (uint32_t)h[2] | ((uint32_t)h[3] << 16);
            packed.z = (uint32_t)h[4] | ((uint32_t)h[5] << 16);
            packed.w = (uint32_t)h[6] | ((uint32_t)h[7] << 16);
            *(uint4*)(g_wh + (size_t)(n0 + nl) * KDIM + k0 + kg * 8) = packed;
        }
    }
}

// ---------------------------------------------------------------------------
// Launch 3: GEMM. A = g_xh [M,K], B = g_wh [N,K] (TN).
// CTA 128x128, 8 warps of 64x32, 3-stage mbarrier pipeline, 2 CTAs/SM.
// smem layout: [0,48) = 3x {full,empty} mbarriers; data tiles from 1024.
// ---------------------------------------------------------------------------
#define A_STAGE_BYTES (BM * BK * 2)          // 16384
#define B_STAGE_BYTES (BN * BK * 2)          // 16384
#define SM_DATA 1024
#define SMEM_TOTAL (SM_DATA + STAGES * (A_STAGE_BYTES + B_STAGE_BYTES))  // 99328

__global__ void __launch_bounds__(256, 2) gemm_kernel(float* __restrict__ out) {
    extern __shared__ char smem[];
    const uint32_t sb = smem_u32(smem);
    const int tid = threadIdx.x;
    const int lane = tid & 31;
    const int wid = tid >> 5;
    const int warp_m = wid & 1;
    const int warp_n = wid >> 1;
    const int m0 = blockIdx.y * BM;
    const int n0 = blockIdx.x * BN;

    // mbarrier addresses
    const uint32_t mb = sb;                  // full(s)=mb+s*16, empty(s)=mb+s*16+8
    const uint32_t db = sb + SM_DATA;        // data base

    if (tid == 0) {
        #pragma unroll
        for (int s = 0; s < STAGES; ++s) {
            MBARRIER_INIT(mb + s * 16, 256);      // full[s]
            MBARRIER_INIT(mb + s * 16 + 8, 256);  // empty[s]
        }
    }
    __syncthreads();

    const uint64_t Ag = __cvta_generic_to_global(g_xh + (size_t)m0 * KDIM);
    const uint64_t Bg = __cvta_generic_to_global(g_wh + (size_t)n0 * KDIM);

    // issue the 8 cp.asyncs of this thread for (stage, kblk); no commit
    auto load_stage = [&](int stage, int kblk) {
        uint32_t abase = db + stage * A_STAGE_BYTES;
        uint32_t bbase = db + STAGES * A_STAGE_BYTES + stage * B_STAGE_BYTES;
        uint64_t koff = (uint64_t)kblk * (BK * 2);
        #pragma unroll
        for (int i = 0; i < 4; ++i) {
            int c = tid + i * 256;
            int row = c >> 3, col = c & 7;
            CP_ASYNC16(abase + SWZ(row * 128 + col * 16),
                       Ag + (uint64_t)row * (KDIM * 2) + koff + col * 16);
        }
        #pragma unroll
        for (int i = 0; i < 4; ++i) {
            int c = tid + i * 256;
            int row = c >> 3, col = c & 7;
            CP_ASYNC16(bbase + SWZ(row * 128 + col * 16),
                       Bg + (uint64_t)row * (KDIM * 2) + koff + col * 16);
        }
    };

    // prologue: k-blocks 0 and 1 into stages 0 and 1
    load_stage(0, 0);
    CP_ASYNC_MBAR_ARRIVE(mb + 0 * 16);
    load_stage(1, 1);
    CP_ASYNC_MBAR_ARRIVE(mb + 1 * 16);

    float acc[4][4][4];
    #pragma unroll
    for (int mi = 0; mi < 4; ++mi)
        #pragma unroll
        for (int nj = 0; nj < 4; ++nj)
            #pragma unroll
            for (int r = 0; r < 4; ++r) acc[mi][nj][r] = 0.0f;

    const uint32_t a_row = warp_m * 64 + (lane & 15);
    const uint32_t a_kb  = (uint32_t)((lane >> 4) << 4);
    const uint32_t b_n   = warp_n * 32 + (lane & 7) + ((lane >> 4) << 3);
    const uint32_t b_kb  = (uint32_t)(((lane >> 3) & 1) << 4);

    // consumer cursor: stage cur, phase curph (round = it/3)
    int cur = 0, curph = 0;
    // producer cursor: k-block pj, stage ps, empty-phase pph = (pj/3 - 1) & 1
    int pj = 2, ps = 2, pph = 1;

    #pragma unroll 1
    for (int it = 0; it < KITERS; ++it) {
        // produce k-block pj = it + 2
        if (pj < KITERS) {
            if (pj >= 3) MBAR_WAIT(mb + ps * 16 + 8, pph);  // empty[ps]
            load_stage(ps, pj);
            CP_ASYNC_MBAR_ARRIVE(mb + ps * 16);             // full[ps]
        }

        // consume k-block it from stage cur
        MBAR_WAIT(mb + cur * 16, curph);                    // full[cur]

        uint32_t abase = db + cur * A_STAGE_BYTES;
        uint32_t bbase = db + STAGES * A_STAGE_BYTES + cur * B_STAGE_BYTES;

        #pragma unroll
        for (int ks = 0; ks < 4; ++ks) {
            uint32_t a[4][4], b[4][2];
            #pragma unroll
            for (int mi = 0; mi < 4; ++mi) {
                uint32_t off = (a_row + mi * 16) * 128 + ks * 32 + a_kb;
                LDSM_X4(a[mi][0], a[mi][1], a[mi][2], a[mi][3], abase + SWZ(off));
            }
            #pragma unroll
            for (int bh = 0; bh < 2; ++bh) {
                uint32_t off = (b_n + bh * 16) * 128 + ks * 32 + b_kb;
                LDSM_X4(b[2 * bh][0], b[2 * bh][1], b[2 * bh + 1][0], b[2 * bh + 1][1],
                        bbase + SWZ(off));
            }
            #pragma unroll
            for (int mi = 0; mi < 4; ++mi)
                #pragma unroll
                for (int nj = 0; nj < 4; ++nj)
                    MMA16816(acc[mi][nj], a[mi], b[nj]);
        }

        MBARRIER_ARRIVE(mb + cur * 16 + 8);                 // empty[cur]

        // advance cursors
        pj++; ps++; if (ps == STAGES) { ps = 0; pph ^= 1; }
        cur++; if (cur == STAGES) { cur = 0; curph ^= 1; }
    }

    // epilogue: scale + store fp32
    const float cs = g_scales[2];
    const int row_base = m0 + warp_m * 64 + (lane >> 2);
    const int col_base = n0 + warp_n * 32 + (lane & 3) * 2;
    #pragma unroll
    for (int mi = 0; mi < 4; ++mi) {
        #pragma unroll
        for (int nj = 0; nj < 4; ++nj) {
            int r = row_base + mi * 16;
            int c = col_base + nj * 8;
            float2 v0 = make_float2(acc[mi][nj][0] * cs, acc[mi][nj][1] * cs);
            float2 v1 = make_float2(acc[mi][nj][2] * cs, acc[mi][nj][3] * cs);
            *(float2*)(out + (size_t)r * NDIM + c) = v0;
            *(float2*)(out + (size_t)(r + 8) * NDIM + c) = v1;
        }
    }
}

// ---------------------------------------------------------------------------
// Launch: exactly 4 kernels
// ---------------------------------------------------------------------------
extern "C" void kernel_launch(void* const* d_in, const int* in_sizes, int n_in,
                              void* d_out, int out_size) {
    const float* x = (const float*)d_in[0];
    const float* w = (const float*)d_in[1];
    float* out = (float*)d_out;

    cudaFuncSetAttribute(gemm_kernel, cudaFuncAttributeMaxDynamicSharedMemorySize, SMEM_TOTAL);

    amax_all_kernel<<<2560, 256>>>(x, w);
    scale_kernel<<<1, 1>>>();
    quant_all_kernel<<<32768 + 1024, 256>>>(x, w);
    gemm_kernel<<<dim3(NDIM / BN, MDIM / BM), 256, SMEM_TOTAL>>>(out);
}